// round 12
// baseline (speedup 1.0000x reference)
#include <cuda_runtime.h>

#define N_PTS 160000
#define C 64
#define SCALE_XY 2073600
/* x,y < 480 (48m / 0.1m): used pids are [0,690240) u [SCALE_XY, SCALE_XY+690240).
   cid = pid - (pid>=SCALE_XY)*1383360 is order-preserving over used pids. */
#define HALF_CID 690240
#define BSHIFT (SCALE_XY - HALF_CID)        /* 1,383,360 */
#define CID_SPACE (2*HALF_CID)              /* 1,380,480 */
#define WORDS (CID_SPACE/2)                 /* 690,240 u32 words, 2 cids/word */
#define SCAN_BLK 256
#define WPT 8
#define TILE_W (SCAN_BLK*WPT)               /* 2048 words */
#define NB1 ((WORDS + TILE_W - 1)/TILE_W)   /* 338 */
#define WORDS_PAD (NB1*TILE_W)              /* 692,224 */

#define FLAG_AGG (1ULL << 62)
#define FLAG_PRE (2ULL << 62)
#define VAL_MASK ((1ULL << 50) - 1)

// ---------------- static scratch (zero-initialized at module load) -----------
// Self-cleaning for graph replay: k_scan zeroes zmask as it reads and g_s/g_m
// after the BN fold; k_link zeroes g_state; k_stats zeroes g_nocc.
__device__ unsigned int       g_zmask32[WORDS_PAD];  // 2 cids/word, 16 z-bits each
__device__ unsigned long long g_info[CID_SPACE];     // (vbase<<16)|zmask, occupied cids only
__device__ unsigned long long g_occ[N_PTS/2];        // (rank<<34)|(vbase<<16)|zmask, nv>=2 pillars
__device__ int                g_head[N_PTS];         // per-voxel point-list head (-1)
__device__ int                g_next[N_PTS];         // per-point list link
__device__ unsigned char      g_zi[N_PTS];           // per-point z bin
__device__ unsigned long long g_state[NB1];          // decoupled-lookback tile state
__device__ double             g_s[8];
__device__ double             g_m[36];
__device__ float              g_W2[512];             // W * BN scale (folded)
__device__ float              g_shift[C];
__device__ int                g_nocc;                // # occupied (nv>=2) pillars

__device__ __forceinline__ int to_cid(int pid) {
    return pid - (pid >= SCALE_XY ? BSHIFT : 0);
}
__device__ __forceinline__ unsigned long long pack_ov(unsigned w) {
    unsigned occ = (unsigned)((w & 0xffffu) != 0u) + (unsigned)((w >> 16) != 0u);
    return ((unsigned long long)occ << 32) | (unsigned)__popc(w);
}
__device__ __forceinline__ unsigned long long vload(const unsigned long long* p) {
    return *(volatile const unsigned long long*)p;
}
__device__ __forceinline__ void vstore(unsigned long long* p, unsigned long long v) {
    *(volatile unsigned long long*)p = v;
}

// -------- moments + zmask + z side-channel --------
__global__ void k_stats(const float* __restrict__ pts, const int* __restrict__ pmc) {
    float s[8]; float m[36];
    #pragma unroll
    for (int k = 0; k < 8; k++) s[k] = 0.f;
    #pragma unroll
    for (int k = 0; k < 36; k++) m[k] = 0.f;

    int tid = blockIdx.x * blockDim.x + threadIdx.x;
    if (tid == 0) g_nocc = 0;               // reset for this replay (before k_scan)
    int stride = gridDim.x * blockDim.x;
    for (int i = tid; i < N_PTS; i += stride) {
        const float* p = pts + (size_t)i * 9;
        float x[8];
        #pragma unroll
        for (int k = 0; k < 8; k++) x[k] = p[1 + k];
        #pragma unroll
        for (int k = 0; k < 8; k++) {
            s[k] += x[k];
            #pragma unroll
            for (int l = 0; l <= k; l++) m[k * (k + 1) / 2 + l] += x[k] * x[l];
        }
        int zi = (int)x[5];                 // z in [0,16), voxel z size 1
        g_zi[i] = (unsigned char)zi;
        int cid = to_cid(pmc[i]);
        atomicOr(&g_zmask32[cid >> 1], (1u << zi) << ((cid & 1) * 16));
    }
    #pragma unroll
    for (int o = 16; o > 0; o >>= 1) {
        #pragma unroll
        for (int k = 0; k < 8; k++)  s[k] += __shfl_down_sync(0xffffffffu, s[k], o);
        #pragma unroll
        for (int k = 0; k < 36; k++) m[k] += __shfl_down_sync(0xffffffffu, m[k], o);
    }
    __shared__ double sd[44];
    if (threadIdx.x < 44) sd[threadIdx.x] = 0.0;
    __syncthreads();
    if ((threadIdx.x & 31) == 0) {
        for (int k = 0; k < 8;  k++) atomicAdd(&sd[k],     (double)s[k]);
        for (int k = 0; k < 36; k++) atomicAdd(&sd[8 + k], (double)m[k]);
    }
    __syncthreads();
    if (threadIdx.x < 8)                      atomicAdd(&g_s[threadIdx.x],     sd[threadIdx.x]);
    if (threadIdx.x >= 8 && threadIdx.x < 44) atomicAdd(&g_m[threadIdx.x - 8], sd[threadIdx.x]);
}

// ---- single-pass scan + lookback + downsweep(info + occ-compact) + BN -------
__global__ void k_scan(const float* __restrict__ W,
                       const float* __restrict__ gamma,
                       const float* __restrict__ beta) {
    __shared__ unsigned long long s_warp[8];
    __shared__ unsigned long long s_agg;
    __shared__ unsigned long long s_exc;
    int t = threadIdx.x;
    int lane = t & 31, wid = t >> 5;
    int bid = blockIdx.x;

    // head fill (-1), spread over scan blocks, coalesced, independent of scan
    {
        int per = (N_PTS / 4 + NB1 - 1) / NB1;           // int4 units per block
        int j0 = bid * per + t;
        int j1 = min((bid + 1) * per, N_PTS / 4);
        int4 m1 = make_int4(-1, -1, -1, -1);
        for (int j = j0; j < j1; j += SCAN_BLK) ((int4*)g_head)[j] = m1;
    }

    size_t base = (size_t)bid * TILE_W + (size_t)t * WPT;
    uint4 a = *(const uint4*)&g_zmask32[base];
    uint4 b = *(const uint4*)&g_zmask32[base + 4];
    // self-clean: zero zmask for the next graph replay (only k_scan reads it)
    uint4 z4 = make_uint4(0u, 0u, 0u, 0u);
    *(uint4*)&g_zmask32[base] = z4;
    *(uint4*)&g_zmask32[base + 4] = z4;
    unsigned w[8] = {a.x, a.y, a.z, a.w, b.x, b.y, b.z, b.w};
    unsigned long long pre[8], run = 0ULL;
    #pragma unroll
    for (int k = 0; k < 8; k++) { pre[k] = run; run += pack_ov(w[k]); }

    unsigned long long inc = run;
    #pragma unroll
    for (int o = 1; o < 32; o <<= 1) {
        unsigned long long v = __shfl_up_sync(0xffffffffu, inc, o);
        if (lane >= o) inc += v;
    }
    if (lane == 31) s_warp[wid] = inc;
    __syncthreads();
    if (t < 8) {
        unsigned long long x = s_warp[t];
        unsigned long long sc = x;
        #pragma unroll
        for (int o = 1; o < 8; o <<= 1) {
            unsigned long long v = __shfl_up_sync(0xffu, sc, o);
            if (t >= o) sc += v;
        }
        s_warp[t] = sc - x;
        if (t == 7) s_agg = sc;
    }
    __syncthreads();

    if (wid == 0) {
        unsigned long long agg = s_agg;
        if (bid == 0) {
            if (lane == 0) { vstore(&g_state[0], FLAG_PRE | agg); s_exc = 0ULL; }
        } else {
            if (lane == 0) vstore(&g_state[bid], FLAG_AGG | agg);
            unsigned long long exc = 0ULL;
            int end = bid;
            while (end > 0) {
                int start = end - 32; if (start < 0) start = 0;
                int j = start + lane;
                bool active = (j < end);
                unsigned long long st = 0ULL;
                do {
                    if (active) st = vload(&g_state[j]);
                } while (__any_sync(0xffffffffu, active && (st >> 62) == 0ULL));
                unsigned pm = __ballot_sync(0xffffffffu, active && (st >> 62) == 2ULL);
                unsigned long long val = active ? (st & VAL_MASK) : 0ULL;
                if (pm) {
                    int hp = 31 - __clz(pm);
                    if (lane < hp) val = 0ULL;
                    #pragma unroll
                    for (int o = 16; o > 0; o >>= 1) val += __shfl_down_sync(0xffffffffu, val, o);
                    exc += val;
                    break;
                } else {
                    #pragma unroll
                    for (int o = 16; o > 0; o >>= 1) val += __shfl_down_sync(0xffffffffu, val, o);
                    exc += val;
                    end = start;
                }
            }
            if (lane == 0) {
                unsigned long long incl = exc + agg;
                vstore(&g_state[bid], FLAG_PRE | incl);
                s_exc = exc;
            }
        }
    }
    __syncthreads();

    unsigned long long e = s_exc + s_warp[wid] + (inc - run);
    #pragma unroll
    for (int k = 0; k < 8; k++) {
        unsigned ww = w[k];
        if (ww) {
            unsigned long long ee = e + pre[k];
            int cid0 = (int)((base + k) * 2);
            unsigned lo = ww & 0xffffu, hi = ww >> 16;
            if (lo) {
                unsigned long long vb = ee & 0xffffffffULL;
                g_info[cid0] = (vb << 16) | lo;
                if (__popc(lo) >= 2) {
                    int q = atomicAdd(&g_nocc, 1);
                    g_occ[q] = ((ee >> 32) << 34) | (vb << 16) | lo;
                }
                ee += (1ULL << 32) + (unsigned)__popc(lo);
            }
            if (hi) {
                unsigned long long vb = ee & 0xffffffffULL;
                g_info[cid0 + 1] = (vb << 16) | hi;
                if (__popc(hi) >= 2) {
                    int q = atomicAdd(&g_nocc, 1);
                    g_occ[q] = ((ee >> 32) << 34) | (vb << 16) | hi;
                }
            }
        }
    }

    // BN fold — block 0 (no lookback wait); overlaps other blocks' lookback
    if (bid == 0 && t >= 64 && t < 128) {
        int c = t - 64;
        double wc[8];
        #pragma unroll
        for (int k = 0; k < 8; k++) wc[k] = (double)W[k * 64 + c];
        const double invn = 1.0 / (double)N_PTS;
        double mu = 0.0;
        #pragma unroll
        for (int k = 0; k < 8; k++) mu += g_s[k] * invn * wc[k];
        double e2 = 0.0;
        #pragma unroll
        for (int k = 0; k < 8; k++) {
            for (int l = 0; l < k; l++) e2 += 2.0 * g_m[k * (k + 1) / 2 + l] * invn * wc[k] * wc[l];
            e2 += g_m[k * (k + 1) / 2 + k] * invn * wc[k] * wc[k];
        }
        double var = e2 - mu * mu;
        double scale = (double)gamma[c] / sqrt(var + 1e-3);
        #pragma unroll
        for (int k = 0; k < 8; k++) g_W2[k * 64 + c] = (float)(wc[k] * scale);
        g_shift[c] = (float)((double)beta[c] - mu * scale);
    }
    __syncthreads();                        // all BN readers of g_s/g_m done
    if (bid == 0 && t < 44) {               // self-clean moments for next replay
        if (t < 8) g_s[t] = 0.0; else g_m[t - 8] = 0.0;
    }
}

// -------- per-voxel point linked lists + g_state self-clean -------------------
__global__ void k_link(const int* __restrict__ pmc) {
    int i = blockIdx.x * blockDim.x + threadIdx.x;   // grid covers N_PTS exactly
    if (i < NB1) g_state[i] = 0ULL;                  // reset lookback state for next replay
    int cid = to_cid(__ldg(&pmc[i]));
    int zi = (int)g_zi[i];
    unsigned long long info = g_info[cid];           // (vbase<<16)|zmask, one sector
    unsigned zm = (unsigned)(info & 0xffffu);
    int slot = (int)(info >> 16) + __popc(zm & ((1u << zi) - 1u));
    g_next[i] = atomicExch(&g_head[slot], i);
}

// -------- pure stream: out = sparse for ALL rows (no divergence) --------------
__global__ void k_copy(float* __restrict__ out, const float* __restrict__ sparse) {
    const float4* src = (const float4*)sparse;
    float4* dst = (float4*)out;
    int n4 = N_PTS * 16;                             // 2.56M float4
    int stride = gridDim.x * blockDim.x;
    for (int j = blockIdx.x * blockDim.x + threadIdx.x; j < n4; j += stride)
        dst[j] = src[j];
}

// -------- heavy: occupied pillars only; overwrite out[r] ----------------------
__global__ void k_heavy(float* __restrict__ out,
                        const float* __restrict__ sparse,
                        const float* __restrict__ pts) {
    __shared__ float sW2[512];
    __shared__ float sSh[64];
    int t = threadIdx.x;
    for (int j = t; j < 512; j += 256) sW2[j] = g_W2[j];
    if (t < 64) sSh[t] = g_shift[t];
    __syncthreads();
    int g = t >> 4, lane = t & 15;
    int nocc = g_nocc;
    int c0 = lane * 4;
    for (int q = blockIdx.x * 16 + g; q < nocc; q += gridDim.x * 16) {
        unsigned long long e = g_occ[q];             // coalesced-ish u64
        unsigned zm = (unsigned)(e & 0xffffu);
        int base = (int)((e >> 16) & 0x3ffffULL);
        int r    = (int)(e >> 34);
        int nv = __popc(zm);                         // >= 2 by construction
        float4 sv = ((const float4*)sparse)[(size_t)r * 16 + lane];
        float4 mx = make_float4(-3.4e38f, -3.4e38f, -3.4e38f, -3.4e38f);
        for (int j = 0; j < nv; j++) {
            int idx = g_head[base + j];
            float a0 = 0.f, a1 = 0.f, a2 = 0.f, a3 = 0.f;
            int cnt = 0;
            while (idx >= 0) {
                const float* p = pts + (size_t)idx * 9;
                int nxt = g_next[idx];
                float x[8];
                #pragma unroll
                for (int k = 0; k < 8; k++) x[k] = __ldg(&p[1 + k]);
                float h0 = sSh[c0], h1 = sSh[c0 + 1], h2 = sSh[c0 + 2], h3 = sSh[c0 + 3];
                #pragma unroll
                for (int k = 0; k < 8; k++) {
                    h0 = fmaf(x[k], sW2[k * 64 + c0],     h0);
                    h1 = fmaf(x[k], sW2[k * 64 + c0 + 1], h1);
                    h2 = fmaf(x[k], sW2[k * 64 + c0 + 2], h2);
                    h3 = fmaf(x[k], sW2[k * 64 + c0 + 3], h3);
                }
                a0 += fmaxf(h0, 0.f); a1 += fmaxf(h1, 0.f);
                a2 += fmaxf(h2, 0.f); a3 += fmaxf(h3, 0.f);
                cnt++;
                idx = nxt;
            }
            float ic = 1.0f / (float)cnt;
            mx.x = fmaxf(mx.x, a0 * ic);
            mx.y = fmaxf(mx.y, a1 * ic);
            mx.z = fmaxf(mx.z, a2 * ic);
            mx.w = fmaxf(mx.w, a3 * ic);
        }
        // voxel mean = sv + mean(relu); zero rows join the max when nv < 16
        float4 cand = make_float4(sv.x + mx.x, sv.y + mx.y, sv.z + mx.z, sv.w + mx.w);
        if (nv < 16) {
            cand.x = fmaxf(cand.x, 0.f); cand.y = fmaxf(cand.y, 0.f);
            cand.z = fmaxf(cand.z, 0.f); cand.w = fmaxf(cand.w, 0.f);
        }
        float4 res = make_float4(sv.x + cand.x, sv.y + cand.y, sv.z + cand.z, sv.w + cand.w);
        ((float4*)out)[(size_t)r * 16 + lane] = res;
    }
}

// ---------------- launch: 5 kernels ----------------
extern "C" void kernel_launch(void* const* d_in, const int* in_sizes, int n_in,
                              void* d_out, int out_size) {
    const float* pts    = (const float*)d_in[0];  // [N,9]
    const float* sparse = (const float*)d_in[1];  // [N,64]
    const float* W      = (const float*)d_in[2];  // [8,64]
    const float* gamma  = (const float*)d_in[3];  // [64]
    const float* beta   = (const float*)d_in[4];  // [64]
    const int*   pmc    = (const int*)d_in[5];    // [N]
    float* out = (float*)d_out;

    k_stats<<<148, 256>>>(pts, pmc);
    k_scan <<<NB1, SCAN_BLK>>>(W, gamma, beta);
    k_link <<<N_PTS / 256, 256>>>(pmc);
    k_copy <<<2368, 256>>>(out, sparse);
    k_heavy<<<1184, 256>>>(out, sparse, pts);
}

// round 13
// speedup vs baseline: 1.0742x; 1.0742x over previous
#include <cuda_runtime.h>

#define N_PTS 160000
#define C 64
#define SCALE_XY 2073600
/* x,y < 480 (48m / 0.1m): used pids are [0,690240) u [SCALE_XY, SCALE_XY+690240).
   cid = pid - (pid>=SCALE_XY)*1383360 is order-preserving over used pids. */
#define HALF_CID 690240
#define BSHIFT (SCALE_XY - HALF_CID)        /* 1,383,360 */
#define CID_SPACE (2*HALF_CID)              /* 1,380,480 */
#define WORDS (CID_SPACE/2)                 /* 690,240 u32 words, 2 cids/word */
#define SCAN_BLK 256
#define WPT 8
#define TILE_W (SCAN_BLK*WPT)               /* 2048 words */
#define NB1 ((WORDS + TILE_W - 1)/TILE_W)   /* 338 */
#define WORDS_PAD (NB1*TILE_W)              /* 692,224 */

#define OCCW (N_PTS/32)                     /* 5000 u32 occupancy-bit words */
#define HEAVY_BLK 384
#define FIN_BLK 2368

#define FLAG_AGG (1ULL << 62)
#define FLAG_PRE (2ULL << 62)
#define VAL_MASK ((1ULL << 50) - 1)

// ---------------- static scratch (zero-initialized at module load) -----------
// Self-cleaning for graph replay: k_scan zeroes zmask as it reads + g_s/g_m
// after BN fold; k_link zeroes g_state; k_stats zeroes g_nocc + g_occbits.
__device__ unsigned int       g_zmask32[WORDS_PAD];  // 2 cids/word, 16 z-bits each
__device__ unsigned long long g_info[CID_SPACE];     // (vbase<<16)|zmask, occupied cids only
__device__ unsigned long long g_occ[N_PTS/2];        // (rank<<34)|(vbase<<16)|zmask, nv>=2
__device__ unsigned int       g_occbits[OCCW];       // rank-indexed nv>=2 bitmap
__device__ int                g_head[N_PTS];         // per-voxel point-list head (-1)
__device__ int                g_next[N_PTS];         // per-point list link
__device__ unsigned char      g_zi[N_PTS];           // per-point z bin
__device__ unsigned long long g_state[NB1];          // decoupled-lookback tile state
__device__ double             g_s[8];
__device__ double             g_m[36];
__device__ float              g_W2[512];             // W * BN scale (folded)
__device__ float              g_shift[C];
__device__ int                g_nocc;                // # occupied (nv>=2) pillars

__device__ __forceinline__ int to_cid(int pid) {
    return pid - (pid >= SCALE_XY ? BSHIFT : 0);
}
__device__ __forceinline__ unsigned long long pack_ov(unsigned w) {
    unsigned occ = (unsigned)((w & 0xffffu) != 0u) + (unsigned)((w >> 16) != 0u);
    return ((unsigned long long)occ << 32) | (unsigned)__popc(w);
}
__device__ __forceinline__ unsigned long long vload(const unsigned long long* p) {
    return *(volatile const unsigned long long*)p;
}
__device__ __forceinline__ void vstore(unsigned long long* p, unsigned long long v) {
    *(volatile unsigned long long*)p = v;
}

// -------- moments + zmask + z side-channel + bitmap/nocc reset --------
__global__ void k_stats(const float* __restrict__ pts, const int* __restrict__ pmc) {
    float s[8]; float m[36];
    #pragma unroll
    for (int k = 0; k < 8; k++) s[k] = 0.f;
    #pragma unroll
    for (int k = 0; k < 36; k++) m[k] = 0.f;

    int tid = blockIdx.x * blockDim.x + threadIdx.x;
    if (tid == 0) g_nocc = 0;
    if (tid < OCCW) g_occbits[tid] = 0u;    // reset bitmap (set later by k_scan)
    int stride = gridDim.x * blockDim.x;
    for (int i = tid; i < N_PTS; i += stride) {
        const float* p = pts + (size_t)i * 9;
        float x[8];
        #pragma unroll
        for (int k = 0; k < 8; k++) x[k] = p[1 + k];
        #pragma unroll
        for (int k = 0; k < 8; k++) {
            s[k] += x[k];
            #pragma unroll
            for (int l = 0; l <= k; l++) m[k * (k + 1) / 2 + l] += x[k] * x[l];
        }
        int zi = (int)x[5];                 // z in [0,16), voxel z size 1
        g_zi[i] = (unsigned char)zi;
        int cid = to_cid(pmc[i]);
        atomicOr(&g_zmask32[cid >> 1], (1u << zi) << ((cid & 1) * 16));
    }
    #pragma unroll
    for (int o = 16; o > 0; o >>= 1) {
        #pragma unroll
        for (int k = 0; k < 8; k++)  s[k] += __shfl_down_sync(0xffffffffu, s[k], o);
        #pragma unroll
        for (int k = 0; k < 36; k++) m[k] += __shfl_down_sync(0xffffffffu, m[k], o);
    }
    __shared__ double sd[44];
    if (threadIdx.x < 44) sd[threadIdx.x] = 0.0;
    __syncthreads();
    if ((threadIdx.x & 31) == 0) {
        for (int k = 0; k < 8;  k++) atomicAdd(&sd[k],     (double)s[k]);
        for (int k = 0; k < 36; k++) atomicAdd(&sd[8 + k], (double)m[k]);
    }
    __syncthreads();
    if (threadIdx.x < 8)                      atomicAdd(&g_s[threadIdx.x],     sd[threadIdx.x]);
    if (threadIdx.x >= 8 && threadIdx.x < 44) atomicAdd(&g_m[threadIdx.x - 8], sd[threadIdx.x]);
}

// ---- single-pass scan + lookback + downsweep(info + occ + bitmap) + BN ------
__global__ void k_scan(const float* __restrict__ W,
                       const float* __restrict__ gamma,
                       const float* __restrict__ beta) {
    __shared__ unsigned long long s_warp[8];
    __shared__ unsigned long long s_agg;
    __shared__ unsigned long long s_exc;
    int t = threadIdx.x;
    int lane = t & 31, wid = t >> 5;
    int bid = blockIdx.x;

    // head fill (-1), spread over scan blocks, coalesced, independent of scan
    {
        int per = (N_PTS / 4 + NB1 - 1) / NB1;
        int j0 = bid * per + t;
        int j1 = min((bid + 1) * per, N_PTS / 4);
        int4 m1 = make_int4(-1, -1, -1, -1);
        for (int j = j0; j < j1; j += SCAN_BLK) ((int4*)g_head)[j] = m1;
    }

    size_t base = (size_t)bid * TILE_W + (size_t)t * WPT;
    uint4 a = *(const uint4*)&g_zmask32[base];
    uint4 b = *(const uint4*)&g_zmask32[base + 4];
    uint4 z4 = make_uint4(0u, 0u, 0u, 0u);   // self-clean zmask for next replay
    *(uint4*)&g_zmask32[base] = z4;
    *(uint4*)&g_zmask32[base + 4] = z4;
    unsigned w[8] = {a.x, a.y, a.z, a.w, b.x, b.y, b.z, b.w};
    unsigned long long pre[8], run = 0ULL;
    #pragma unroll
    for (int k = 0; k < 8; k++) { pre[k] = run; run += pack_ov(w[k]); }

    unsigned long long inc = run;
    #pragma unroll
    for (int o = 1; o < 32; o <<= 1) {
        unsigned long long v = __shfl_up_sync(0xffffffffu, inc, o);
        if (lane >= o) inc += v;
    }
    if (lane == 31) s_warp[wid] = inc;
    __syncthreads();
    if (t < 8) {
        unsigned long long x = s_warp[t];
        unsigned long long sc = x;
        #pragma unroll
        for (int o = 1; o < 8; o <<= 1) {
            unsigned long long v = __shfl_up_sync(0xffu, sc, o);
            if (t >= o) sc += v;
        }
        s_warp[t] = sc - x;
        if (t == 7) s_agg = sc;
    }
    __syncthreads();

    if (wid == 0) {
        unsigned long long agg = s_agg;
        if (bid == 0) {
            if (lane == 0) { vstore(&g_state[0], FLAG_PRE | agg); s_exc = 0ULL; }
        } else {
            if (lane == 0) vstore(&g_state[bid], FLAG_AGG | agg);
            unsigned long long exc = 0ULL;
            int end = bid;
            while (end > 0) {
                int start = end - 32; if (start < 0) start = 0;
                int j = start + lane;
                bool active = (j < end);
                unsigned long long st = 0ULL;
                do {
                    if (active) st = vload(&g_state[j]);
                } while (__any_sync(0xffffffffu, active && (st >> 62) == 0ULL));
                unsigned pm = __ballot_sync(0xffffffffu, active && (st >> 62) == 2ULL);
                unsigned long long val = active ? (st & VAL_MASK) : 0ULL;
                if (pm) {
                    int hp = 31 - __clz(pm);
                    if (lane < hp) val = 0ULL;
                    #pragma unroll
                    for (int o = 16; o > 0; o >>= 1) val += __shfl_down_sync(0xffffffffu, val, o);
                    exc += val;
                    break;
                } else {
                    #pragma unroll
                    for (int o = 16; o > 0; o >>= 1) val += __shfl_down_sync(0xffffffffu, val, o);
                    exc += val;
                    end = start;
                }
            }
            if (lane == 0) {
                unsigned long long incl = exc + agg;
                vstore(&g_state[bid], FLAG_PRE | incl);
                s_exc = exc;
            }
        }
    }
    __syncthreads();

    unsigned long long e = s_exc + s_warp[wid] + (inc - run);
    #pragma unroll
    for (int k = 0; k < 8; k++) {
        unsigned ww = w[k];
        if (ww) {
            unsigned long long ee = e + pre[k];
            int cid0 = (int)((base + k) * 2);
            unsigned lo = ww & 0xffffu, hi = ww >> 16;
            if (lo) {
                unsigned long long vb = ee & 0xffffffffULL;
                g_info[cid0] = (vb << 16) | lo;
                if (__popc(lo) >= 2) {
                    int rank = (int)(ee >> 32);
                    int q = atomicAdd(&g_nocc, 1);
                    g_occ[q] = ((unsigned long long)rank << 34) | (vb << 16) | lo;
                    atomicOr(&g_occbits[rank >> 5], 1u << (rank & 31));
                }
                ee += (1ULL << 32) + (unsigned)__popc(lo);
            }
            if (hi) {
                unsigned long long vb = ee & 0xffffffffULL;
                g_info[cid0 + 1] = (vb << 16) | hi;
                if (__popc(hi) >= 2) {
                    int rank = (int)(ee >> 32);
                    int q = atomicAdd(&g_nocc, 1);
                    g_occ[q] = ((unsigned long long)rank << 34) | (vb << 16) | hi;
                    atomicOr(&g_occbits[rank >> 5], 1u << (rank & 31));
                }
            }
        }
    }

    // BN fold — block 0 (no lookback wait); overlaps other blocks' lookback
    if (bid == 0 && t >= 64 && t < 128) {
        int c = t - 64;
        double wc[8];
        #pragma unroll
        for (int k = 0; k < 8; k++) wc[k] = (double)W[k * 64 + c];
        const double invn = 1.0 / (double)N_PTS;
        double mu = 0.0;
        #pragma unroll
        for (int k = 0; k < 8; k++) mu += g_s[k] * invn * wc[k];
        double e2 = 0.0;
        #pragma unroll
        for (int k = 0; k < 8; k++) {
            for (int l = 0; l < k; l++) e2 += 2.0 * g_m[k * (k + 1) / 2 + l] * invn * wc[k] * wc[l];
            e2 += g_m[k * (k + 1) / 2 + k] * invn * wc[k] * wc[k];
        }
        double var = e2 - mu * mu;
        double scale = (double)gamma[c] / sqrt(var + 1e-3);
        #pragma unroll
        for (int k = 0; k < 8; k++) g_W2[k * 64 + c] = (float)(wc[k] * scale);
        g_shift[c] = (float)((double)beta[c] - mu * scale);
    }
    __syncthreads();
    if (bid == 0 && t < 44) {               // self-clean moments for next replay
        if (t < 8) g_s[t] = 0.0; else g_m[t - 8] = 0.0;
    }
}

// -------- per-voxel point linked lists + g_state self-clean -------------------
__global__ void k_link(const int* __restrict__ pmc) {
    int i = blockIdx.x * blockDim.x + threadIdx.x;   // grid covers N_PTS exactly
    if (i < NB1) g_state[i] = 0ULL;                  // reset lookback state
    int cid = to_cid(__ldg(&pmc[i]));
    int zi = (int)g_zi[i];
    unsigned long long info = g_info[cid];           // (vbase<<16)|zmask, one sector
    unsigned zm = (unsigned)(info & 0xffffu);
    int slot = (int)(info >> 16) + __popc(zm & ((1u << zi) - 1u));
    g_next[i] = atomicExch(&g_head[slot], i);
}

// -------- fused final: heavy blocks + stream blocks, DISJOINT row sets --------
__global__ void k_fin(float* __restrict__ out,
                      const float* __restrict__ sparse,
                      const float* __restrict__ pts) {
    int t = threadIdx.x, bid = blockIdx.x;
    if (bid < HEAVY_BLK) {
        // ----- heavy: occupied pillars from compact worklist -----
        __shared__ float sW2[512];
        __shared__ float sSh[64];
        for (int j = t; j < 512; j += 256) sW2[j] = g_W2[j];
        if (t < 64) sSh[t] = g_shift[t];
        __syncthreads();
        int g = t >> 4, lane = t & 15;
        int c0 = lane * 4;
        int nocc = g_nocc;
        for (int q = bid * 16 + g; q < nocc; q += HEAVY_BLK * 16) {
            unsigned long long e = g_occ[q];
            unsigned zm = (unsigned)(e & 0xffffu);
            int base = (int)((e >> 16) & 0x3ffffULL);
            int r    = (int)(e >> 34);
            int nv = __popc(zm);                     // >= 2 by construction
            float4 sv = ((const float4*)sparse)[(size_t)r * 16 + lane];
            float4 mx = make_float4(-3.4e38f, -3.4e38f, -3.4e38f, -3.4e38f);
            for (int j = 0; j < nv; j++) {
                int idx = g_head[base + j];
                float a0 = 0.f, a1 = 0.f, a2 = 0.f, a3 = 0.f;
                int cnt = 0;
                while (idx >= 0) {
                    const float* p = pts + (size_t)idx * 9;
                    int nxt = g_next[idx];
                    float x[8];
                    #pragma unroll
                    for (int k = 0; k < 8; k++) x[k] = __ldg(&p[1 + k]);
                    float h0 = sSh[c0], h1 = sSh[c0 + 1], h2 = sSh[c0 + 2], h3 = sSh[c0 + 3];
                    #pragma unroll
                    for (int k = 0; k < 8; k++) {
                        h0 = fmaf(x[k], sW2[k * 64 + c0],     h0);
                        h1 = fmaf(x[k], sW2[k * 64 + c0 + 1], h1);
                        h2 = fmaf(x[k], sW2[k * 64 + c0 + 2], h2);
                        h3 = fmaf(x[k], sW2[k * 64 + c0 + 3], h3);
                    }
                    a0 += fmaxf(h0, 0.f); a1 += fmaxf(h1, 0.f);
                    a2 += fmaxf(h2, 0.f); a3 += fmaxf(h3, 0.f);
                    cnt++;
                    idx = nxt;
                }
                float ic = 1.0f / (float)cnt;
                mx.x = fmaxf(mx.x, a0 * ic);
                mx.y = fmaxf(mx.y, a1 * ic);
                mx.z = fmaxf(mx.z, a2 * ic);
                mx.w = fmaxf(mx.w, a3 * ic);
            }
            float4 cand = make_float4(sv.x + mx.x, sv.y + mx.y, sv.z + mx.z, sv.w + mx.w);
            if (nv < 16) {
                cand.x = fmaxf(cand.x, 0.f); cand.y = fmaxf(cand.y, 0.f);
                cand.z = fmaxf(cand.z, 0.f); cand.w = fmaxf(cand.w, 0.f);
            }
            ((float4*)out)[(size_t)r * 16 + lane] =
                make_float4(sv.x + cand.x, sv.y + cand.y, sv.z + cand.z, sv.w + cand.w);
        }
    } else {
        // ----- stream: out = sparse for rows NOT in the bitmap -----
        const float4* src = (const float4*)sparse;
        float4* dst = (float4*)out;
        int n4 = N_PTS * 16;
        int stride = (FIN_BLK - HEAVY_BLK) * 256;
        for (int j = (bid - HEAVY_BLK) * 256 + t; j < n4; j += stride) {
            int r = j >> 4;
            if (!((g_occbits[r >> 5] >> (r & 31)) & 1u))
                dst[j] = src[j];
        }
    }
}

// ---------------- launch: 4 kernels ----------------
extern "C" void kernel_launch(void* const* d_in, const int* in_sizes, int n_in,
                              void* d_out, int out_size) {
    const float* pts    = (const float*)d_in[0];  // [N,9]
    const float* sparse = (const float*)d_in[1];  // [N,64]
    const float* W      = (const float*)d_in[2];  // [8,64]
    const float* gamma  = (const float*)d_in[3];  // [64]
    const float* beta   = (const float*)d_in[4];  // [64]
    const int*   pmc    = (const int*)d_in[5];    // [N]
    float* out = (float*)d_out;

    k_stats<<<148, 256>>>(pts, pmc);
    k_scan <<<NB1, SCAN_BLK>>>(W, gamma, beta);
    k_link <<<N_PTS / 256, 256>>>(pmc);
    k_fin  <<<FIN_BLK, 256>>>(out, sparse, pts);
}